// round 5
// baseline (speedup 1.0000x reference)
#include <cuda_runtime.h>

#define T_STEPS 512

// ---- packed f32x2 helpers (sm_100+ PTX) ----
__device__ __forceinline__ unsigned long long pack2(float lo, float hi){
    unsigned long long r;
    asm("mov.b64 %0, {%1, %2};" : "=l"(r) : "f"(lo), "f"(hi));
    return r;
}
__device__ __forceinline__ void ffma2(unsigned long long& acc, unsigned long long a, unsigned long long b){
    asm("fma.rn.f32x2 %0, %1, %2, %0;" : "+l"(acc) : "l"(a), "l"(b));
}
__device__ __forceinline__ float2 unpack2(unsigned long long v){
    float2 f;
    asm("mov.b64 {%0, %1}, %2;" : "=f"(f.x), "=f"(f.y) : "l"(v));
    return f;
}
__device__ __forceinline__ float fast_exp2(float x){
    float r; asm("ex2.approx.f32 %0, %1;" : "=f"(r) : "f"(x)); return r;
}
__device__ __forceinline__ float fast_rcp(float x){
    float r; asm("rcp.approx.f32 %0, %1;" : "=f"(r) : "f"(x)); return r;
}
__device__ __forceinline__ float sigmoidf_(float x){
    return fast_rcp(1.0f + fast_exp2(-1.4426950408889634f * x));
}
__device__ __forceinline__ float tanhf_(float x){
    float e = fast_exp2(-2.8853900817779268f * x);
    return fmaf(2.0f, fast_rcp(1.0f + e), -1.0f);
}

// K-SPLIT design: one block = 2 warps = 2 batch elements.
// Warp w holds W_hh[:, w*16 .. w*16+16) => only 64 weight regs/thread.
// Per step:
//   1) each warp computes k-half partial dots for BOTH batches (64 FFMA2)
//   2) exchange: warp w stores the other batch's 4 partials -> __syncthreads
//   3) warp w finishes gates/c/h for batch w ONLY (10 MUFU, no redundancy),
//      writes h_t to shared slab -> __syncthreads (both warps read both h's)
// Low regs => 14 warps/SM resident => one wave @ 3.46 warps/SMSP,
// enough concurrency to hide LDS/MUFU/barrier latency behind the FMA pipe.
__global__ void __launch_bounds__(64, 7) lstm_ksplit(
    const float* __restrict__ x,
    const float* __restrict__ W_ih,
    const float* __restrict__ W_hh,
    const float* __restrict__ b_ih,
    const float* __restrict__ b_hh,
    const float* __restrict__ W_fc,
    const float* __restrict__ b_fc,
    float* __restrict__ out,
    int B)
{
    const int tid  = threadIdx.x;
    const int lane = tid & 31;
    const int wid  = tid >> 5;          // 0 or 1: k-half AND gate-batch owner
    const int b0 = blockIdx.x * 2;
    const int bw = b0 + wid;            // batch this warp gates
    const int bwm = (bw < B) ? bw : b0; // safe dup for odd B

    // h slab: [batch][step][36]; 36-float row stride keeps rows 16B aligned.
    __shared__ __align__(16) float hs[2][32][36];
    __shared__ float pex[2][4][32];     // [writer warp][gate][lane]
    __shared__ float wfcs[32];

    // ---- per-warp weight k-half: 4 gate rows x 8 f32x2 pairs = 64 regs ----
    unsigned long long w2[4][8];
    unsigned long long wx2[4];
    float bias[4];
#pragma unroll
    for (int r = 0; r < 4; r++){
        const int row = r * 32 + lane;
        const float4* wr = reinterpret_cast<const float4*>(W_hh) + row * 8 + wid * 4;
#pragma unroll
        for (int q = 0; q < 4; q++){
            float4 v = wr[q];
            w2[r][2*q]   = pack2(v.x, v.y);
            w2[r][2*q+1] = pack2(v.z, v.w);
        }
        wx2[r]  = pack2(W_ih[row*2 + 0], W_ih[row*2 + 1]);
        bias[r] = b_ih[row] + b_hh[row];
    }
    const float bfc = b_fc[0];

    if (wid == 0){
        hs[0][31][lane] = 0.0f;         // h_{-1} = 0 (read by step 0)
        hs[1][31][lane] = 0.0f;
        wfcs[lane] = W_fc[lane];
    }
    __syncthreads();

    float c = 0.0f;                     // cell state of batch bw (this warp)
    const float2* xrw = reinterpret_cast<const float2*>(x) + (size_t)bwm * T_STEPS;
    float2 xv = xrw[0];
    const int kq = wid * 4;             // ulonglong2 offset of my k-half
    const int ob = wid ^ 1;             // other warp / other batch

    for (int tb = 0; tb < T_STEPS / 32; tb++){
#pragma unroll 1
        for (int ts = 0; ts < 32; ts++){
            const int t  = (tb << 5) + ts;
            const int tn = (t + 1 < T_STEPS) ? (t + 1) : t;
            float2 xn = xrw[tn];                          // prefetch own-batch x

            const int rp = (ts + 31) & 31;                // row holding h_{t-1}
            const ulonglong2* h0p = reinterpret_cast<const ulonglong2*>(&hs[0][rp][0]) + kq;
            const ulonglong2* h1p = reinterpret_cast<const ulonglong2*>(&hs[1][rp][0]) + kq;

            // partial dots over my 16-wide k-half, both batches, 4 gates each
            unsigned long long a00 = 0ull, a01 = 0ull, a02 = 0ull, a03 = 0ull;
            unsigned long long a10 = 0ull, a11 = 0ull, a12 = 0ull, a13 = 0ull;
#pragma unroll
            for (int q = 0; q < 4; q++){
                ulonglong2 v0 = h0p[q];
                ulonglong2 v1 = h1p[q];
                ffma2(a00, v0.x, w2[0][2*q]);   ffma2(a01, v0.x, w2[1][2*q]);
                ffma2(a02, v0.x, w2[2][2*q]);   ffma2(a03, v0.x, w2[3][2*q]);
                ffma2(a10, v1.x, w2[0][2*q]);   ffma2(a11, v1.x, w2[1][2*q]);
                ffma2(a12, v1.x, w2[2][2*q]);   ffma2(a13, v1.x, w2[3][2*q]);
                ffma2(a00, v0.y, w2[0][2*q+1]); ffma2(a01, v0.y, w2[1][2*q+1]);
                ffma2(a02, v0.y, w2[2][2*q+1]); ffma2(a03, v0.y, w2[3][2*q+1]);
                ffma2(a10, v1.y, w2[0][2*q+1]); ffma2(a11, v1.y, w2[1][2*q+1]);
                ffma2(a12, v1.y, w2[2][2*q+1]); ffma2(a13, v1.y, w2[3][2*q+1]);
            }

            // combine lo+hi; keep own batch's partials, export other batch's
            float2 u;
            float ps0, ps1, ps2, ps3;
            if (wid == 0){
                u = unpack2(a00); ps0 = u.x + u.y;
                u = unpack2(a01); ps1 = u.x + u.y;
                u = unpack2(a02); ps2 = u.x + u.y;
                u = unpack2(a03); ps3 = u.x + u.y;
                u = unpack2(a10); pex[0][0][lane] = u.x + u.y;
                u = unpack2(a11); pex[0][1][lane] = u.x + u.y;
                u = unpack2(a12); pex[0][2][lane] = u.x + u.y;
                u = unpack2(a13); pex[0][3][lane] = u.x + u.y;
            } else {
                u = unpack2(a10); ps0 = u.x + u.y;
                u = unpack2(a11); ps1 = u.x + u.y;
                u = unpack2(a12); ps2 = u.x + u.y;
                u = unpack2(a13); ps3 = u.x + u.y;
                u = unpack2(a00); pex[1][0][lane] = u.x + u.y;
                u = unpack2(a01); pex[1][1][lane] = u.x + u.y;
                u = unpack2(a02); pex[1][2][lane] = u.x + u.y;
                u = unpack2(a03); pex[1][3][lane] = u.x + u.y;
            }
            __syncthreads();   // partials visible

            // full gate pre-activations for MY batch: own + peer + bias + x-proj
            unsigned long long xp = pack2(xv.x, xv.y);
            unsigned long long t0 = pack2(bias[0], 0.f);
            unsigned long long t1 = pack2(bias[1], 0.f);
            unsigned long long t2 = pack2(bias[2], 0.f);
            unsigned long long t3 = pack2(bias[3], 0.f);
            ffma2(t0, xp, wx2[0]); ffma2(t1, xp, wx2[1]);
            ffma2(t2, xp, wx2[2]); ffma2(t3, xp, wx2[3]);
            float2 f0 = unpack2(t0), f1 = unpack2(t1);
            float2 f2 = unpack2(t2), f3 = unpack2(t3);
            const float g0 = (ps0 + pex[ob][0][lane]) + (f0.x + f0.y);
            const float g1 = (ps1 + pex[ob][1][lane]) + (f1.x + f1.y);
            const float g2 = (ps2 + pex[ob][2][lane]) + (f2.x + f2.y);
            const float g3 = (ps3 + pex[ob][3][lane]) + (f3.x + f3.y);

            const float ig = sigmoidf_(g0);
            const float fg = sigmoidf_(g1);
            const float gg = tanhf_   (g2);
            const float og = sigmoidf_(g3);
            c = fmaf(fg, c, ig * gg);
            const float h = og * tanhf_(c);

            hs[wid][ts][lane] = h;      // publish h_t for both warps
            __syncthreads();

            xv = xn;
        }

        // ---- deferred FC head: warp w outputs its batch, lane j = step j ----
        float p = 0.0f;
#pragma unroll
        for (int k = 0; k < 32; k++)
            p = fmaf(hs[wid][lane][k], wfcs[k], p);
        if (bw < B)
            out[(size_t)bw * T_STEPS + (tb << 5) + lane] = p + bfc;
        __syncwarp();   // FC reads complete before next chunk overwrites rows
    }
}

extern "C" void kernel_launch(void* const* d_in, const int* in_sizes, int n_in,
                              void* d_out, int out_size)
{
    const float* x   = (const float*)d_in[0];
    const float* Wih = (const float*)d_in[1];
    const float* Whh = (const float*)d_in[2];
    const float* bih = (const float*)d_in[3];
    const float* bhh = (const float*)d_in[4];
    const float* Wfc = (const float*)d_in[5];
    const float* bfc = (const float*)d_in[6];
    float* out = (float*)d_out;

    const int B = out_size / T_STEPS;      // OUT=1 -> out_size = B*T
    const int grid = (B + 1) / 2;          // 2 batches per 2-warp block
    lstm_ksplit<<<grid, 64>>>(x, Wih, Whh, bih, bhh, Wfc, bfc, out, B);
}